// round 2
// baseline (speedup 1.0000x reference)
#include <cuda_runtime.h>

// Problem constants
#define BB 2
#define SS 2048
#define DM 1024
#define HH 16
#define DK 64

// Scratch (allocation-free rule: __device__ globals)
__device__ float g_qh[BB*HH*SS*DK];   // 16 MB, [B,H,S,64]
__device__ float g_kh[BB*HH*SS*DK];   // 16 MB
__device__ float g_vh[BB*HH*SS*DK];   // 16 MB
__device__ float g_attn[BB*SS*DM];    // 16 MB, [B,S,D]

// ---------------------------------------------------------------------------
// 64x64 tile GEMM: C[M,N] = A[M,K] @ W[N,K]^T + bias,   K = 1024 fixed.
// 256 threads, each computes a 4x4 micro-tile. Smem transposed (k-major) so
// the inner loop is 2x LDS.128 + 16 FFMA per k-step.
// ---------------------------------------------------------------------------
__device__ __forceinline__ void gemm64(const float* __restrict__ A,
                                       const float* __restrict__ W,
                                       const float* __restrict__ bias,
                                       float* __restrict__ C,
                                       bool splitHead)
{
    __shared__ float As[16][68];
    __shared__ float Ws[16][68];

    const int tid = threadIdx.x;
    const int ty  = tid >> 4;        // 0..15
    const int tx  = tid & 15;        // 0..15
    const int m0  = blockIdx.y << 6;
    const int n0  = blockIdx.x << 6;
    const int lr  = tid >> 2;        // 0..63 (tile row loaded by this thread)
    const int lk  = (tid & 3) << 2;  // 0,4,8,12 (k sub-offset)

    float acc[4][4];
#pragma unroll
    for (int i = 0; i < 4; i++)
#pragma unroll
        for (int j = 0; j < 4; j++) acc[i][j] = 0.f;

    const float* Ap = A + (size_t)(m0 + lr) * 1024 + lk;
    const float* Wp = W + (size_t)(n0 + lr) * 1024 + lk;

    for (int k0 = 0; k0 < 1024; k0 += 16) {
        float4 av = *(const float4*)(Ap + k0);
        float4 wv = *(const float4*)(Wp + k0);
        As[lk + 0][lr] = av.x; As[lk + 1][lr] = av.y;
        As[lk + 2][lr] = av.z; As[lk + 3][lr] = av.w;
        Ws[lk + 0][lr] = wv.x; Ws[lk + 1][lr] = wv.y;
        Ws[lk + 2][lr] = wv.z; Ws[lk + 3][lr] = wv.w;
        __syncthreads();

#pragma unroll
        for (int kk = 0; kk < 16; kk++) {
            float4 a = *(const float4*)&As[kk][ty << 2];
            float4 b = *(const float4*)&Ws[kk][tx << 2];
            float ar[4] = {a.x, a.y, a.z, a.w};
            float br[4] = {b.x, b.y, b.z, b.w};
#pragma unroll
            for (int i = 0; i < 4; i++)
#pragma unroll
                for (int j = 0; j < 4; j++)
                    acc[i][j] += ar[i] * br[j];
        }
        __syncthreads();
    }

#pragma unroll
    for (int i = 0; i < 4; i++) {
        const int m = m0 + (ty << 2) + i;
#pragma unroll
        for (int j = 0; j < 4; j++) {
            const int n = n0 + (tx << 2) + j;
            float val = acc[i][j] + bias[n];
            if (splitHead) {
                // write to [B,H,S,64]
                const int b = m >> 11;          // m / S
                const int s = m & 2047;         // m % S
                const int h = n >> 6;           // n / 64
                const int d = n & 63;           // n % 64
                C[(((size_t)(b * HH + h) * SS) + s) * DK + d] = val;
            } else {
                C[(size_t)m * 1024 + n] = val;
            }
        }
    }
}

__global__ void __launch_bounds__(256)
qkv_proj_kernel(const float* __restrict__ q, const float* __restrict__ k,
                const float* __restrict__ v,
                const float* __restrict__ wq, const float* __restrict__ wk,
                const float* __restrict__ wv,
                const float* __restrict__ bq, const float* __restrict__ bk,
                const float* __restrict__ bv)
{
    const float *A, *W, *bias;
    float* C;
    if (blockIdx.z == 0)      { A = q; W = wq; bias = bq; C = g_qh; }
    else if (blockIdx.z == 1) { A = k; W = wk; bias = bk; C = g_kh; }
    else                      { A = v; W = wv; bias = bv; C = g_vh; }
    gemm64(A, W, bias, C, true);
}

__global__ void __launch_bounds__(256)
out_proj_kernel(const float* __restrict__ wo, const float* __restrict__ bo,
                float* __restrict__ out)
{
    gemm64(g_attn, wo, bo, out, false);
}

// ---------------------------------------------------------------------------
// Flash attention: one CTA per (q-block of 64, head, batch).
// Br = Bc = 64, d_k = 64, 32 KV tiles. 256 threads, 4x4 micro-tiles.
// Score cols use c = tx + 16*j (conflict-free strided smem reads),
// O/V cols use d = 4*tx + j (LDS.128). Pt aliases Ks smem.
// ---------------------------------------------------------------------------
__global__ void __launch_bounds__(256, 2)
flash_kernel(const int* __restrict__ mask)
{
    extern __shared__ float sm[];
    float* Qs = sm;                  // [64][64] row-major
    float* Ks = sm + 64 * 64;        // [64][68] row-major (aliased as Pt)
    float* Vs = Ks + 64 * 68;        // [64][64] row-major

    const int b  = blockIdx.z;
    const int h  = blockIdx.y;
    const int q0 = blockIdx.x << 6;
    const int tid = threadIdx.x;
    const int ty = tid >> 4;   // 0..15
    const int tx = tid & 15;   // 0..15

    const float* Qg = g_qh + ((size_t)(b * HH + h) * SS + q0) * DK;
    const float* Kg = g_kh + ((size_t)(b * HH + h) * SS) * DK;
    const float* Vg = g_vh + ((size_t)(b * HH + h) * SS) * DK;

    // Load Q tile (vectorized, coalesced)
    {
        const int r  = tid >> 4;          // 0..15
        const int dq = (tid & 15) << 2;   // 0..60 step 4
#pragma unroll
        for (int it = 0; it < 4; it++) {
            const int rr = r + (it << 4);
            *(float4*)&Qs[rr * 64 + dq] = *(const float4*)&Qg[(size_t)rr * 64 + dq];
        }
    }

    float o[4][4];
#pragma unroll
    for (int i = 0; i < 4; i++)
#pragma unroll
        for (int j = 0; j < 4; j++) o[i][j] = 0.f;
    float mrun[4] = {-3e38f, -3e38f, -3e38f, -3e38f};
    float lrun[4] = {0.f, 0.f, 0.f, 0.f};

    for (int t = 0; t < 32; t++) {
        const int k0 = t << 6;
        __syncthreads();  // previous tile's Pt/Vs readers done (also covers Qs on t=0)

        // Load K,V tiles
        {
            const int r  = tid >> 4;
            const int dq = (tid & 15) << 2;
#pragma unroll
            for (int it = 0; it < 4; it++) {
                const int rr = r + (it << 4);
                *(float4*)&Ks[rr * 68 + dq] = *(const float4*)&Kg[(size_t)(k0 + rr) * 64 + dq];
                *(float4*)&Vs[rr * 64 + dq] = *(const float4*)&Vg[(size_t)(k0 + rr) * 64 + dq];
            }
        }
        __syncthreads();

        // Preload mask for this thread's 16 score elements
        int mv[4][4];
#pragma unroll
        for (int i = 0; i < 4; i++) {
            const int mrow = q0 + ty + (i << 4);
#pragma unroll
            for (int j = 0; j < 4; j++)
                mv[i][j] = mask[(size_t)mrow * SS + (k0 + tx + (j << 4))];
        }

        // S = Q @ K^T
        float s[4][4];
#pragma unroll
        for (int i = 0; i < 4; i++)
#pragma unroll
            for (int j = 0; j < 4; j++) s[i][j] = 0.f;

#pragma unroll
        for (int dq4 = 0; dq4 < 64; dq4 += 4) {
            float4 qv[4], kv[4];
#pragma unroll
            for (int i = 0; i < 4; i++)
                qv[i] = *(const float4*)&Qs[(ty + (i << 4)) * 64 + dq4];
#pragma unroll
            for (int j = 0; j < 4; j++)
                kv[j] = *(const float4*)&Ks[(tx + (j << 4)) * 68 + dq4];
#pragma unroll
            for (int i = 0; i < 4; i++)
#pragma unroll
                for (int j = 0; j < 4; j++)
                    s[i][j] += qv[i].x * kv[j].x + qv[i].y * kv[j].y +
                               qv[i].z * kv[j].z + qv[i].w * kv[j].w;
        }

        // scale + mask
#pragma unroll
        for (int i = 0; i < 4; i++)
#pragma unroll
            for (int j = 0; j < 4; j++)
                s[i][j] = mv[i][j] ? s[i][j] * 0.125f : -1e9f;

        // Online softmax (row reduction over the 16 tx lanes of the half-warp)
#pragma unroll
        for (int i = 0; i < 4; i++) {
            float mx = fmaxf(fmaxf(s[i][0], s[i][1]), fmaxf(s[i][2], s[i][3]));
#pragma unroll
            for (int off = 1; off < 16; off <<= 1)
                mx = fmaxf(mx, __shfl_xor_sync(0xffffffffu, mx, off));
            const float mn = fmaxf(mrun[i], mx);
            const float alpha = __expf(mrun[i] - mn);
            mrun[i] = mn;
            float r0 = 0.f;
#pragma unroll
            for (int j = 0; j < 4; j++) {
                s[i][j] = __expf(s[i][j] - mn);
                r0 += s[i][j];
            }
#pragma unroll
            for (int off = 1; off < 16; off <<= 1)
                r0 += __shfl_xor_sync(0xffffffffu, r0, off);
            lrun[i] = lrun[i] * alpha + r0;
#pragma unroll
            for (int jj = 0; jj < 4; jj++) o[i][jj] *= alpha;
        }

        __syncthreads();  // all threads done reading Ks before aliasing as Pt
        float* Pt = Ks;   // [64 rows (q)][68 stride], col = kv index
#pragma unroll
        for (int i = 0; i < 4; i++)
#pragma unroll
            for (int j = 0; j < 4; j++)
                Pt[(ty + (i << 4)) * 68 + (tx + (j << 4))] = s[i][j];
        __syncthreads();

        // O += P @ V   (d columns = 4*tx + jj, LDS.128 on both operands)
#pragma unroll
        for (int jq = 0; jq < 64; jq += 4) {
            float4 pv[4], vv[4];
#pragma unroll
            for (int i = 0; i < 4; i++)
                pv[i] = *(const float4*)&Pt[(ty + (i << 4)) * 68 + jq];
#pragma unroll
            for (int u = 0; u < 4; u++)
                vv[u] = *(const float4*)&Vs[(jq + u) * 64 + (tx << 2)];
#pragma unroll
            for (int i = 0; i < 4; i++) {
                o[i][0] += pv[i].x * vv[0].x + pv[i].y * vv[1].x + pv[i].z * vv[2].x + pv[i].w * vv[3].x;
                o[i][1] += pv[i].x * vv[0].y + pv[i].y * vv[1].y + pv[i].z * vv[2].y + pv[i].w * vv[3].y;
                o[i][2] += pv[i].x * vv[0].z + pv[i].y * vv[1].z + pv[i].z * vv[2].z + pv[i].w * vv[3].z;
                o[i][3] += pv[i].x * vv[0].w + pv[i].y * vv[1].w + pv[i].z * vv[2].w + pv[i].w * vv[3].w;
            }
        }
    }

    // Write O / l to g_attn in [B,S,D] layout (merging heads)
    float* Og = g_attn + ((size_t)b * SS + q0) * DM + h * DK;
#pragma unroll
    for (int i = 0; i < 4; i++) {
        const float inv = 1.0f / lrun[i];
        const int r = ty + (i << 4);
#pragma unroll
        for (int jj = 0; jj < 4; jj++)
            Og[(size_t)r * DM + (tx << 2) + jj] = o[i][jj] * inv;
    }
}

// ---------------------------------------------------------------------------
extern "C" void kernel_launch(void* const* d_in, const int* in_sizes, int n_in,
                              void* d_out, int out_size)
{
    const float* q    = (const float*)d_in[0];
    const float* k    = (const float*)d_in[1];
    const float* v    = (const float*)d_in[2];
    const int*   mask = (const int*)  d_in[3];
    const float* wq   = (const float*)d_in[4];
    const float* bq   = (const float*)d_in[5];
    const float* wk   = (const float*)d_in[6];
    const float* bk   = (const float*)d_in[7];
    const float* wv   = (const float*)d_in[8];
    const float* bv   = (const float*)d_in[9];
    const float* wo   = (const float*)d_in[10];
    const float* bo   = (const float*)d_in[11];
    float* out = (float*)d_out;

    const int FLASH_SMEM = (64 * 64 + 64 * 68 + 64 * 64) * 4;  // 50176 B
    cudaFuncSetAttribute(flash_kernel, cudaFuncAttributeMaxDynamicSharedMemorySize,
                         FLASH_SMEM);

    dim3 blk(256);
    // QKV projections: M=4096, N=1024 in 64x64 tiles; z selects q/k/v
    qkv_proj_kernel<<<dim3(16, 64, 3), blk>>>(q, k, v, wq, wk, wv, bq, bk, bv);
    // Flash attention: (32 q-blocks, 16 heads, 2 batches)
    flash_kernel<<<dim3(32, 16, 2), blk, FLASH_SMEM>>>(mask);
    // Output projection
    out_proj_kernel<<<dim3(16, 64, 1), blk>>>(wo, bo, out);
}

// round 3
// speedup vs baseline: 1.0013x; 1.0013x over previous
#include <cuda_runtime.h>

// Problem constants
#define BB 2
#define SS 2048
#define DM 1024
#define HH 16
#define DK 64

// Scratch (allocation-free rule: __device__ globals)
__device__ float g_qh[BB*HH*SS*DK];   // 16 MB, [B,H,S,64]
__device__ float g_kh[BB*HH*SS*DK];   // 16 MB
__device__ float g_vh[BB*HH*SS*DK];   // 16 MB
__device__ float g_attn[BB*SS*DM];    // 16 MB, [B,S,D]

// ---------------------------------------------------------------------------
// 64x64 tile GEMM: C[M,N] = A[M,K] @ W[N,K]^T + bias,   K = 1024 fixed.
// 256 threads, each computes a 4x4 micro-tile. Smem transposed (k-major) so
// the inner loop is 2x LDS.128 + 16 FFMA per k-step.
// ---------------------------------------------------------------------------
__device__ __forceinline__ void gemm64(const float* __restrict__ A,
                                       const float* __restrict__ W,
                                       const float* __restrict__ bias,
                                       float* __restrict__ C,
                                       bool splitHead)
{
    __shared__ float As[16][68];
    __shared__ float Ws[16][68];

    const int tid = threadIdx.x;
    const int ty  = tid >> 4;        // 0..15
    const int tx  = tid & 15;        // 0..15
    const int m0  = blockIdx.y << 6;
    const int n0  = blockIdx.x << 6;
    const int lr  = tid >> 2;        // 0..63 (tile row loaded by this thread)
    const int lk  = (tid & 3) << 2;  // 0,4,8,12 (k sub-offset)

    float acc[4][4];
#pragma unroll
    for (int i = 0; i < 4; i++)
#pragma unroll
        for (int j = 0; j < 4; j++) acc[i][j] = 0.f;

    const float* Ap = A + (size_t)(m0 + lr) * 1024 + lk;
    const float* Wp = W + (size_t)(n0 + lr) * 1024 + lk;

    for (int k0 = 0; k0 < 1024; k0 += 16) {
        float4 av = *(const float4*)(Ap + k0);
        float4 wv = *(const float4*)(Wp + k0);
        As[lk + 0][lr] = av.x; As[lk + 1][lr] = av.y;
        As[lk + 2][lr] = av.z; As[lk + 3][lr] = av.w;
        Ws[lk + 0][lr] = wv.x; Ws[lk + 1][lr] = wv.y;
        Ws[lk + 2][lr] = wv.z; Ws[lk + 3][lr] = wv.w;
        __syncthreads();

#pragma unroll
        for (int kk = 0; kk < 16; kk++) {
            float4 a = *(const float4*)&As[kk][ty << 2];
            float4 b = *(const float4*)&Ws[kk][tx << 2];
            float ar[4] = {a.x, a.y, a.z, a.w};
            float br[4] = {b.x, b.y, b.z, b.w};
#pragma unroll
            for (int i = 0; i < 4; i++)
#pragma unroll
                for (int j = 0; j < 4; j++)
                    acc[i][j] += ar[i] * br[j];
        }
        __syncthreads();
    }

#pragma unroll
    for (int i = 0; i < 4; i++) {
        const int m = m0 + (ty << 2) + i;
#pragma unroll
        for (int j = 0; j < 4; j++) {
            const int n = n0 + (tx << 2) + j;
            float val = acc[i][j] + bias[n];
            if (splitHead) {
                // write to [B,H,S,64]
                const int b = m >> 11;          // m / S
                const int s = m & 2047;         // m % S
                const int h = n >> 6;           // n / 64
                const int d = n & 63;           // n % 64
                C[(((size_t)(b * HH + h) * SS) + s) * DK + d] = val;
            } else {
                C[(size_t)m * 1024 + n] = val;
            }
        }
    }
}

__global__ void __launch_bounds__(256)
qkv_proj_kernel(const float* __restrict__ q, const float* __restrict__ k,
                const float* __restrict__ v,
                const float* __restrict__ wq, const float* __restrict__ wk,
                const float* __restrict__ wv,
                const float* __restrict__ bq, const float* __restrict__ bk,
                const float* __restrict__ bv)
{
    const float *A, *W, *bias;
    float* C;
    if (blockIdx.z == 0)      { A = q; W = wq; bias = bq; C = g_qh; }
    else if (blockIdx.z == 1) { A = k; W = wk; bias = bk; C = g_kh; }
    else                      { A = v; W = wv; bias = bv; C = g_vh; }
    gemm64(A, W, bias, C, true);
}

__global__ void __launch_bounds__(256)
out_proj_kernel(const float* __restrict__ wo, const float* __restrict__ bo,
                float* __restrict__ out)
{
    gemm64(g_attn, wo, bo, out, false);
}

// ---------------------------------------------------------------------------
// Flash attention: one CTA per (q-block of 64, head, batch).
// Br = Bc = 64, d_k = 64, 32 KV tiles. 256 threads, 4x4 micro-tiles.
// Score cols use c = tx + 16*j (conflict-free strided smem reads),
// O/V cols use d = 4*tx + j (LDS.128). Pt aliases Ks smem.
// ---------------------------------------------------------------------------
__global__ void __launch_bounds__(256, 2)
flash_kernel(const int* __restrict__ mask)
{
    extern __shared__ float sm[];
    float* Qs = sm;                  // [64][64] row-major
    float* Ks = sm + 64 * 64;        // [64][68] row-major (aliased as Pt)
    float* Vs = Ks + 64 * 68;        // [64][64] row-major

    const int b  = blockIdx.z;
    const int h  = blockIdx.y;
    const int q0 = blockIdx.x << 6;
    const int tid = threadIdx.x;
    const int ty = tid >> 4;   // 0..15
    const int tx = tid & 15;   // 0..15

    const float* Qg = g_qh + ((size_t)(b * HH + h) * SS + q0) * DK;
    const float* Kg = g_kh + ((size_t)(b * HH + h) * SS) * DK;
    const float* Vg = g_vh + ((size_t)(b * HH + h) * SS) * DK;

    // Load Q tile (vectorized, coalesced)
    {
        const int r  = tid >> 4;          // 0..15
        const int dq = (tid & 15) << 2;   // 0..60 step 4
#pragma unroll
        for (int it = 0; it < 4; it++) {
            const int rr = r + (it << 4);
            *(float4*)&Qs[rr * 64 + dq] = *(const float4*)&Qg[(size_t)rr * 64 + dq];
        }
    }

    float o[4][4];
#pragma unroll
    for (int i = 0; i < 4; i++)
#pragma unroll
        for (int j = 0; j < 4; j++) o[i][j] = 0.f;
    float mrun[4] = {-3e38f, -3e38f, -3e38f, -3e38f};
    float lrun[4] = {0.f, 0.f, 0.f, 0.f};

    for (int t = 0; t < 32; t++) {
        const int k0 = t << 6;
        __syncthreads();  // previous tile's Pt/Vs readers done (also covers Qs on t=0)

        // Load K,V tiles
        {
            const int r  = tid >> 4;
            const int dq = (tid & 15) << 2;
#pragma unroll
            for (int it = 0; it < 4; it++) {
                const int rr = r + (it << 4);
                *(float4*)&Ks[rr * 68 + dq] = *(const float4*)&Kg[(size_t)(k0 + rr) * 64 + dq];
                *(float4*)&Vs[rr * 64 + dq] = *(const float4*)&Vg[(size_t)(k0 + rr) * 64 + dq];
            }
        }
        __syncthreads();

        // Preload mask for this thread's 16 score elements
        int mv[4][4];
#pragma unroll
        for (int i = 0; i < 4; i++) {
            const int mrow = q0 + ty + (i << 4);
#pragma unroll
            for (int j = 0; j < 4; j++)
                mv[i][j] = mask[(size_t)mrow * SS + (k0 + tx + (j << 4))];
        }

        // S = Q @ K^T
        float s[4][4];
#pragma unroll
        for (int i = 0; i < 4; i++)
#pragma unroll
            for (int j = 0; j < 4; j++) s[i][j] = 0.f;

#pragma unroll
        for (int dq4 = 0; dq4 < 64; dq4 += 4) {
            float4 qv[4], kv[4];
#pragma unroll
            for (int i = 0; i < 4; i++)
                qv[i] = *(const float4*)&Qs[(ty + (i << 4)) * 64 + dq4];
#pragma unroll
            for (int j = 0; j < 4; j++)
                kv[j] = *(const float4*)&Ks[(tx + (j << 4)) * 68 + dq4];
#pragma unroll
            for (int i = 0; i < 4; i++)
#pragma unroll
                for (int j = 0; j < 4; j++)
                    s[i][j] += qv[i].x * kv[j].x + qv[i].y * kv[j].y +
                               qv[i].z * kv[j].z + qv[i].w * kv[j].w;
        }

        // scale + mask
#pragma unroll
        for (int i = 0; i < 4; i++)
#pragma unroll
            for (int j = 0; j < 4; j++)
                s[i][j] = mv[i][j] ? s[i][j] * 0.125f : -1e9f;

        // Online softmax (row reduction over the 16 tx lanes of the half-warp)
#pragma unroll
        for (int i = 0; i < 4; i++) {
            float mx = fmaxf(fmaxf(s[i][0], s[i][1]), fmaxf(s[i][2], s[i][3]));
#pragma unroll
            for (int off = 1; off < 16; off <<= 1)
                mx = fmaxf(mx, __shfl_xor_sync(0xffffffffu, mx, off));
            const float mn = fmaxf(mrun[i], mx);
            const float alpha = __expf(mrun[i] - mn);
            mrun[i] = mn;
            float r0 = 0.f;
#pragma unroll
            for (int j = 0; j < 4; j++) {
                s[i][j] = __expf(s[i][j] - mn);
                r0 += s[i][j];
            }
#pragma unroll
            for (int off = 1; off < 16; off <<= 1)
                r0 += __shfl_xor_sync(0xffffffffu, r0, off);
            lrun[i] = lrun[i] * alpha + r0;
#pragma unroll
            for (int jj = 0; jj < 4; jj++) o[i][jj] *= alpha;
        }

        __syncthreads();  // all threads done reading Ks before aliasing as Pt
        float* Pt = Ks;   // [64 rows (q)][68 stride], col = kv index
#pragma unroll
        for (int i = 0; i < 4; i++)
#pragma unroll
            for (int j = 0; j < 4; j++)
                Pt[(ty + (i << 4)) * 68 + (tx + (j << 4))] = s[i][j];
        __syncthreads();

        // O += P @ V   (d columns = 4*tx + jj, LDS.128 on both operands)
#pragma unroll
        for (int jq = 0; jq < 64; jq += 4) {
            float4 pv[4], vv[4];
#pragma unroll
            for (int i = 0; i < 4; i++)
                pv[i] = *(const float4*)&Pt[(ty + (i << 4)) * 68 + jq];
#pragma unroll
            for (int u = 0; u < 4; u++)
                vv[u] = *(const float4*)&Vs[(jq + u) * 64 + (tx << 2)];
#pragma unroll
            for (int i = 0; i < 4; i++) {
                o[i][0] += pv[i].x * vv[0].x + pv[i].y * vv[1].x + pv[i].z * vv[2].x + pv[i].w * vv[3].x;
                o[i][1] += pv[i].x * vv[0].y + pv[i].y * vv[1].y + pv[i].z * vv[2].y + pv[i].w * vv[3].y;
                o[i][2] += pv[i].x * vv[0].z + pv[i].y * vv[1].z + pv[i].z * vv[2].z + pv[i].w * vv[3].z;
                o[i][3] += pv[i].x * vv[0].w + pv[i].y * vv[1].w + pv[i].z * vv[2].w + pv[i].w * vv[3].w;
            }
        }
    }

    // Write O / l to g_attn in [B,S,D] layout (merging heads)
    float* Og = g_attn + ((size_t)b * SS + q0) * DM + h * DK;
#pragma unroll
    for (int i = 0; i < 4; i++) {
        const float inv = 1.0f / lrun[i];
        const int r = ty + (i << 4);
#pragma unroll
        for (int jj = 0; jj < 4; jj++)
            Og[(size_t)r * DM + (tx << 2) + jj] = o[i][jj] * inv;
    }
}

// ---------------------------------------------------------------------------
extern "C" void kernel_launch(void* const* d_in, const int* in_sizes, int n_in,
                              void* d_out, int out_size)
{
    const float* q    = (const float*)d_in[0];
    const float* k    = (const float*)d_in[1];
    const float* v    = (const float*)d_in[2];
    const int*   mask = (const int*)  d_in[3];
    const float* wq   = (const float*)d_in[4];
    const float* bq   = (const float*)d_in[5];
    const float* wk   = (const float*)d_in[6];
    const float* bk   = (const float*)d_in[7];
    const float* wv   = (const float*)d_in[8];
    const float* bv   = (const float*)d_in[9];
    const float* wo   = (const float*)d_in[10];
    const float* bo   = (const float*)d_in[11];
    float* out = (float*)d_out;

    const int FLASH_SMEM = (64 * 64 + 64 * 68 + 64 * 64) * 4;  // 50176 B
    cudaFuncSetAttribute(flash_kernel, cudaFuncAttributeMaxDynamicSharedMemorySize,
                         FLASH_SMEM);

    dim3 blk(256);
    // QKV projections: M=4096, N=1024 in 64x64 tiles; z selects q/k/v
    qkv_proj_kernel<<<dim3(16, 64, 3), blk>>>(q, k, v, wq, wk, wv, bq, bk, bv);
    // Flash attention: (32 q-blocks, 16 heads, 2 batches)
    flash_kernel<<<dim3(32, 16, 2), blk, FLASH_SMEM>>>(mask);
    // Output projection
    out_proj_kernel<<<dim3(16, 64, 1), blk>>>(wo, bo, out);
}

// round 4
// speedup vs baseline: 1.0315x; 1.0302x over previous
#include <cuda_runtime.h>

#define BB 2
#define SS 2048
#define DM 1024
#define HH 16
#define DK 64

typedef unsigned long long ull;

// Scratch (allocation-free rule: __device__ globals)
__device__ float g_qh[BB*HH*SS*DK];   // [B,H,S,64]
__device__ float g_kh[BB*HH*SS*DK];
__device__ float g_vh[BB*HH*SS*DK];
__device__ float g_attn[BB*SS*DM];    // [B,S,D]

// ---------------- packed f32x2 helpers (sm_10x) ----------------
__device__ __forceinline__ void fma2(ull& d, ull a, ull b) {
    asm("fma.rn.f32x2 %0, %1, %2, %0;" : "+l"(d) : "l"(a), "l"(b));
}
__device__ __forceinline__ void mul2(ull& d, ull a) {
    asm("mul.rn.f32x2 %0, %0, %1;" : "+l"(d) : "l"(a));
}
__device__ __forceinline__ ull dup2(float x) {
    ull r; asm("mov.b64 %0, {%1, %1};" : "=l"(r) : "f"(x)); return r;
}
__device__ __forceinline__ float2 unpack2(ull v) {
    float2 f; asm("mov.b64 {%0, %1}, %2;" : "=f"(f.x), "=f"(f.y) : "l"(v)); return f;
}

// ---------------------------------------------------------------------------
// 128x128 tile GEMM: C[M,N] = A[M,K] @ W[N,K]^T + bias, K=1024.
// 256 threads, 8x8 micro-tile, accumulators packed (f32x2) along N.
// ---------------------------------------------------------------------------
__device__ __forceinline__ void gemm128(const float* __restrict__ A,
                                        const float* __restrict__ W,
                                        const float* __restrict__ bias,
                                        float* __restrict__ C,
                                        bool splitHead)
{
    __shared__ float As[16][132];   // k-major slab, transposed
    __shared__ float Ws[16][132];

    const int tid = threadIdx.x;
    const int ty  = tid >> 4;        // 0..15
    const int tx  = tid & 15;        // 0..15
    const int m0  = blockIdx.y << 7;
    const int n0  = blockIdx.x << 7;
    const int lrow = tid >> 1;       // 0..127
    const int lk4  = (tid & 1) << 3; // 0 or 8

    ull acc2[8][4];
#pragma unroll
    for (int i = 0; i < 8; i++)
#pragma unroll
        for (int j = 0; j < 4; j++) acc2[i][j] = 0ull;

    const float* Ap = A + (size_t)(m0 + lrow) * 1024 + lk4;
    const float* Wp = W + (size_t)(n0 + lrow) * 1024 + lk4;

    for (int k0 = 0; k0 < 1024; k0 += 16) {
        float4 av0 = *(const float4*)(Ap + k0);
        float4 av1 = *(const float4*)(Ap + k0 + 4);
        float4 wv0 = *(const float4*)(Wp + k0);
        float4 wv1 = *(const float4*)(Wp + k0 + 4);
        __syncthreads();
        As[lk4+0][lrow] = av0.x; As[lk4+1][lrow] = av0.y;
        As[lk4+2][lrow] = av0.z; As[lk4+3][lrow] = av0.w;
        As[lk4+4][lrow] = av1.x; As[lk4+5][lrow] = av1.y;
        As[lk4+6][lrow] = av1.z; As[lk4+7][lrow] = av1.w;
        Ws[lk4+0][lrow] = wv0.x; Ws[lk4+1][lrow] = wv0.y;
        Ws[lk4+2][lrow] = wv0.z; Ws[lk4+3][lrow] = wv0.w;
        Ws[lk4+4][lrow] = wv1.x; Ws[lk4+5][lrow] = wv1.y;
        Ws[lk4+6][lrow] = wv1.z; Ws[lk4+7][lrow] = wv1.w;
        __syncthreads();

#pragma unroll
        for (int kk = 0; kk < 16; kk++) {
            float4 a0 = *(const float4*)&As[kk][ty << 3];
            float4 a1 = *(const float4*)&As[kk][(ty << 3) + 4];
            ulonglong2 b0 = *(const ulonglong2*)&Ws[kk][tx << 3];
            ulonglong2 b1 = *(const ulonglong2*)&Ws[kk][(tx << 3) + 4];
            ull ad[8];
            ad[0] = dup2(a0.x); ad[1] = dup2(a0.y);
            ad[2] = dup2(a0.z); ad[3] = dup2(a0.w);
            ad[4] = dup2(a1.x); ad[5] = dup2(a1.y);
            ad[6] = dup2(a1.z); ad[7] = dup2(a1.w);
#pragma unroll
            for (int i = 0; i < 8; i++) {
                fma2(acc2[i][0], ad[i], b0.x);
                fma2(acc2[i][1], ad[i], b0.y);
                fma2(acc2[i][2], ad[i], b1.x);
                fma2(acc2[i][3], ad[i], b1.y);
            }
        }
    }

#pragma unroll
    for (int i = 0; i < 8; i++) {
        const int m = m0 + (ty << 3) + i;
#pragma unroll
        for (int jp = 0; jp < 4; jp++) {
            const int n = n0 + (tx << 3) + (jp << 1);
            float2 f = unpack2(acc2[i][jp]);
            float v0 = f.x + bias[n];
            float v1 = f.y + bias[n + 1];
            if (splitHead) {
                const int b = m >> 11, s = m & 2047;
                const int h0 = n >> 6, d0 = n & 63;
                float* base = C + (((size_t)(b * HH + h0) * SS) + s) * DK;
                base[d0] = v0;   // n and n+1 share a head (d0 is even, <63)
                base[d0 + 1] = v1;
            } else {
                *(float2*)&C[(size_t)m * 1024 + n] = make_float2(v0, v1);
            }
        }
    }
}

__global__ void __launch_bounds__(256, 2)
qkv_proj_kernel(const float* __restrict__ q, const float* __restrict__ k,
                const float* __restrict__ v,
                const float* __restrict__ wq, const float* __restrict__ wk,
                const float* __restrict__ wv,
                const float* __restrict__ bq, const float* __restrict__ bk,
                const float* __restrict__ bv)
{
    const float *A, *W, *bias; float* C;
    if (blockIdx.z == 0)      { A = q; W = wq; bias = bq; C = g_qh; }
    else if (blockIdx.z == 1) { A = k; W = wk; bias = bk; C = g_kh; }
    else                      { A = v; W = wv; bias = bv; C = g_vh; }
    gemm128(A, W, bias, C, true);
}

__global__ void __launch_bounds__(256, 2)
out_proj_kernel(const float* __restrict__ wo, const float* __restrict__ bo,
                float* __restrict__ out)
{
    gemm128(g_attn, wo, bo, out, false);
}

// ---------------------------------------------------------------------------
// Flash attention, f32x2 math. One CTA per (q-block 64, head, batch).
// QK^T packs the d reduction (pure dots); PV packs output columns;
// O accumulator stays packed across tiles. K/V register-prefetched.
// ---------------------------------------------------------------------------
__global__ void __launch_bounds__(256, 1)
flash_kernel(const int* __restrict__ mask)
{
    extern __shared__ float sm[];
    float* Qs = sm;                  // [64][64]
    float* Ks = sm + 64 * 64;        // [64][68]  (aliased as Pt)
    float* Vs = Ks + 64 * 68;        // [64][64]

    const int b  = blockIdx.z;
    const int h  = blockIdx.y;
    const int q0 = blockIdx.x << 6;
    const int tid = threadIdx.x;
    const int ty = tid >> 4;
    const int tx = tid & 15;
    const int lr  = tid >> 4;          // loader row base
    const int ldq = (tid & 15) << 2;   // loader d offset

    const float* Qg = g_qh + ((size_t)(b * HH + h) * SS + q0) * DK;
    const float* Kg = g_kh + ((size_t)(b * HH + h) * SS) * DK;
    const float* Vg = g_vh + ((size_t)(b * HH + h) * SS) * DK;

    // Load Q tile
#pragma unroll
    for (int it = 0; it < 4; it++) {
        const int rr = lr + (it << 4);
        *(float4*)&Qs[rr * 64 + ldq] = *(const float4*)&Qg[(size_t)rr * 64 + ldq];
    }

    ull o2[4][2];
#pragma unroll
    for (int i = 0; i < 4; i++) { o2[i][0] = 0ull; o2[i][1] = 0ull; }
    float mrun[4] = {-3e38f, -3e38f, -3e38f, -3e38f};
    float lrun[4] = {0.f, 0.f, 0.f, 0.f};

    // Prefetch tile 0 K/V into registers
    float4 kreg[4], vreg[4];
#pragma unroll
    for (int it = 0; it < 4; it++) {
        const int rr = lr + (it << 4);
        kreg[it] = *(const float4*)&Kg[(size_t)rr * 64 + ldq];
        vreg[it] = *(const float4*)&Vg[(size_t)rr * 64 + ldq];
    }

    for (int t = 0; t < 32; t++) {
        const int k0 = t << 6;
        __syncthreads();  // prev tile's Pt/Vs readers done (covers Qs at t=0)

        // Commit prefetched K/V to smem
#pragma unroll
        for (int it = 0; it < 4; it++) {
            const int rr = lr + (it << 4);
            *(float4*)&Ks[rr * 68 + ldq] = kreg[it];
            *(float4*)&Vs[rr * 64 + ldq] = vreg[it];
        }
        __syncthreads();

        // Prefetch next tile
        if (t < 31) {
            const int kn = (t + 1) << 6;
#pragma unroll
            for (int it = 0; it < 4; it++) {
                const int rr = kn + lr + (it << 4);
                kreg[it] = *(const float4*)&Kg[(size_t)rr * 64 + ldq];
                vreg[it] = *(const float4*)&Vg[(size_t)rr * 64 + ldq];
            }
        }

        // Mask for this thread's 16 scores
        int mv[4][4];
#pragma unroll
        for (int i = 0; i < 4; i++) {
            const int mrow = q0 + ty + (i << 4);
#pragma unroll
            for (int j = 0; j < 4; j++)
                mv[i][j] = mask[(size_t)mrow * SS + (k0 + tx + (j << 4))];
        }

        // S = Q @ K^T  (packed along d)
        ull s2[4][4];
#pragma unroll
        for (int i = 0; i < 4; i++)
#pragma unroll
            for (int j = 0; j < 4; j++) s2[i][j] = 0ull;

#pragma unroll
        for (int dq4 = 0; dq4 < 64; dq4 += 4) {
            ulonglong2 qv[4], kv[4];
#pragma unroll
            for (int i = 0; i < 4; i++)
                qv[i] = *(const ulonglong2*)&Qs[(ty + (i << 4)) * 64 + dq4];
#pragma unroll
            for (int j = 0; j < 4; j++)
                kv[j] = *(const ulonglong2*)&Ks[(tx + (j << 4)) * 68 + dq4];
#pragma unroll
            for (int i = 0; i < 4; i++)
#pragma unroll
                for (int j = 0; j < 4; j++) {
                    fma2(s2[i][j], qv[i].x, kv[j].x);
                    fma2(s2[i][j], qv[i].y, kv[j].y);
                }
        }

        // Horizontal add + scale + mask
        float s[4][4];
#pragma unroll
        for (int i = 0; i < 4; i++)
#pragma unroll
            for (int j = 0; j < 4; j++) {
                float2 f = unpack2(s2[i][j]);
                s[i][j] = mv[i][j] ? (f.x + f.y) * 0.125f : -1e9f;
            }

        // Online softmax (rows reduce over 16 tx lanes)
#pragma unroll
        for (int i = 0; i < 4; i++) {
            float mx = fmaxf(fmaxf(s[i][0], s[i][1]), fmaxf(s[i][2], s[i][3]));
#pragma unroll
            for (int off = 1; off < 16; off <<= 1)
                mx = fmaxf(mx, __shfl_xor_sync(0xffffffffu, mx, off));
            const float mn = fmaxf(mrun[i], mx);
            const float alpha = __expf(mrun[i] - mn);
            mrun[i] = mn;
            float r0 = 0.f;
#pragma unroll
            for (int j = 0; j < 4; j++) {
                s[i][j] = __expf(s[i][j] - mn);
                r0 += s[i][j];
            }
#pragma unroll
            for (int off = 1; off < 16; off <<= 1)
                r0 += __shfl_xor_sync(0xffffffffu, r0, off);
            lrun[i] = lrun[i] * alpha + r0;
            ull ad = dup2(alpha);
            mul2(o2[i][0], ad);
            mul2(o2[i][1], ad);
        }

        __syncthreads();  // everyone done reading Ks before alias as Pt
        float* Pt = Ks;   // [64 q-rows][68], col = kv index
#pragma unroll
        for (int i = 0; i < 4; i++)
#pragma unroll
            for (int j = 0; j < 4; j++)
                Pt[(ty + (i << 4)) * 68 + (tx + (j << 4))] = s[i][j];
        __syncthreads();

        // O += P @ V  (packed along output columns, dup P on ALU pipe)
#pragma unroll
        for (int jq = 0; jq < 64; jq += 4) {
            float4 pv[4];
            ulonglong2 vv[4];
#pragma unroll
            for (int i = 0; i < 4; i++)
                pv[i] = *(const float4*)&Pt[(ty + (i << 4)) * 68 + jq];
#pragma unroll
            for (int u = 0; u < 4; u++)
                vv[u] = *(const ulonglong2*)&Vs[(jq + u) * 64 + (tx << 2)];
#pragma unroll
            for (int i = 0; i < 4; i++) {
                ull dx = dup2(pv[i].x), dy = dup2(pv[i].y);
                ull dz = dup2(pv[i].z), dw = dup2(pv[i].w);
                fma2(o2[i][0], dx, vv[0].x); fma2(o2[i][1], dx, vv[0].y);
                fma2(o2[i][0], dy, vv[1].x); fma2(o2[i][1], dy, vv[1].y);
                fma2(o2[i][0], dz, vv[2].x); fma2(o2[i][1], dz, vv[2].y);
                fma2(o2[i][0], dw, vv[3].x); fma2(o2[i][1], dw, vv[3].y);
            }
        }
    }

    // Epilogue: normalize and merge heads into [B,S,D]
    float* Og = g_attn + ((size_t)b * SS + q0) * DM + h * DK;
#pragma unroll
    for (int i = 0; i < 4; i++) {
        const float inv = 1.0f / lrun[i];
        const int r = ty + (i << 4);
#pragma unroll
        for (int jp = 0; jp < 2; jp++) {
            float2 f = unpack2(o2[i][jp]);
            *(float2*)&Og[(size_t)r * DM + (tx << 2) + (jp << 1)] =
                make_float2(f.x * inv, f.y * inv);
        }
    }
}

// ---------------------------------------------------------------------------
extern "C" void kernel_launch(void* const* d_in, const int* in_sizes, int n_in,
                              void* d_out, int out_size)
{
    const float* q    = (const float*)d_in[0];
    const float* k    = (const float*)d_in[1];
    const float* v    = (const float*)d_in[2];
    const int*   mask = (const int*)  d_in[3];
    const float* wq   = (const float*)d_in[4];
    const float* bq   = (const float*)d_in[5];
    const float* wk   = (const float*)d_in[6];
    const float* bk   = (const float*)d_in[7];
    const float* wv   = (const float*)d_in[8];
    const float* bv   = (const float*)d_in[9];
    const float* wo   = (const float*)d_in[10];
    const float* bo   = (const float*)d_in[11];
    float* out = (float*)d_out;

    const int FLASH_SMEM = (64 * 64 + 64 * 68 + 64 * 64) * 4;  // 50176 B
    cudaFuncSetAttribute(flash_kernel, cudaFuncAttributeMaxDynamicSharedMemorySize,
                         FLASH_SMEM);

    dim3 blk(256);
    qkv_proj_kernel<<<dim3(8, 32, 3), blk>>>(q, k, v, wq, wk, wv, bq, bk, bv);
    flash_kernel<<<dim3(32, 16, 2), blk, FLASH_SMEM>>>(mask);
    out_proj_kernel<<<dim3(8, 32, 1), blk>>>(wo, bo, out);
}

// round 6
// speedup vs baseline: 1.5658x; 1.5179x over previous
#include <cuda_runtime.h>
#include <cuda_bf16.h>
#include <cstdint>

#define BB 2
#define SS 2048
#define DM 1024
#define HH 16
#define DK 64

typedef unsigned long long ull;

#define ACT_N ((size_t)4096 * 1024)
#define W_N   ((size_t)1024 * 1024)

// Scratch (__device__ globals; allocation-free rule)
__device__ float g_qh[BB*HH*SS*DK];                 // fp32 [B,H,S,64] for flash
__device__ float g_kh[BB*HH*SS*DK];
__device__ float g_vh[BB*HH*SS*DK];
__device__ __align__(16) __nv_bfloat16 g_act_hi[3 * ACT_N];   // q,k,v split
__device__ __align__(16) __nv_bfloat16 g_act_lo[3 * ACT_N];
__device__ __align__(16) __nv_bfloat16 g_w_hi[4 * W_N];       // wq,wk,wv,wo split
__device__ __align__(16) __nv_bfloat16 g_w_lo[4 * W_N];
__device__ __align__(16) __nv_bfloat16 g_attn_hi[ACT_N];      // flash out split
__device__ __align__(16) __nv_bfloat16 g_attn_lo[ACT_N];

// ---------------- helpers ----------------
__device__ __forceinline__ uint32_t smem_u32(const void* p) {
    uint32_t a;
    asm("{ .reg .u64 t; cvta.to.shared.u64 t, %1; cvt.u32.u64 %0, t; }"
        : "=r"(a) : "l"(p));
    return a;
}
__device__ __forceinline__ void fma2(ull& d, ull a, ull b) {
    asm("fma.rn.f32x2 %0, %1, %2, %0;" : "+l"(d) : "l"(a), "l"(b));
}
__device__ __forceinline__ void mul2(ull& d, ull a) {
    asm("mul.rn.f32x2 %0, %0, %1;" : "+l"(d) : "l"(a));
}
__device__ __forceinline__ ull dup2(float x) {
    ull r; asm("mov.b64 %0, {%1, %1};" : "=l"(r) : "f"(x)); return r;
}
__device__ __forceinline__ float2 unpack2(ull v) {
    float2 f; asm("mov.b64 {%0, %1}, %2;" : "=f"(f.x), "=f"(f.y) : "l"(v)); return f;
}

// mma.sync m16n8k16 bf16 -> fp32
__device__ __forceinline__ void mma16816(float* c, const uint32_t* a, const uint32_t* b) {
    asm volatile(
        "mma.sync.aligned.m16n8k16.row.col.f32.bf16.bf16.f32 "
        "{%0,%1,%2,%3}, {%4,%5,%6,%7}, {%8,%9}, {%0,%1,%2,%3};"
        : "+f"(c[0]), "+f"(c[1]), "+f"(c[2]), "+f"(c[3])
        : "r"(a[0]), "r"(a[1]), "r"(a[2]), "r"(a[3]), "r"(b[0]), "r"(b[1]));
}
__device__ __forceinline__ void ldmx4(uint32_t* r, uint32_t addr) {
    asm volatile("ldmatrix.sync.aligned.m8n8.x4.shared.b16 {%0,%1,%2,%3}, [%4];"
                 : "=r"(r[0]), "=r"(r[1]), "=r"(r[2]), "=r"(r[3]) : "r"(addr));
}
__device__ __forceinline__ void cp16(uint32_t saddr, uint64_t gaddr) {
    asm volatile("cp.async.cg.shared.global [%0], [%1], 16;"
                 :: "r"(saddr), "l"(gaddr) : "memory");
}
#define CP_COMMIT() asm volatile("cp.async.commit_group;" ::: "memory")
#define CP_WAIT(n)  asm volatile("cp.async.wait_group %0;" :: "n"(n) : "memory")

__device__ __forceinline__ uint32_t swz(uint32_t x) { return x ^ ((x >> 3) & 0x70); }

// ---------------------------------------------------------------------------
// Split fp32 -> bf16 hi/lo.  z=0..2: q,k,v ; z=3..6: wq,wk,wv,wo
// ---------------------------------------------------------------------------
__global__ void __launch_bounds__(256)
split_kernel(const float* __restrict__ q, const float* __restrict__ k,
             const float* __restrict__ v,
             const float* __restrict__ wq, const float* __restrict__ wk,
             const float* __restrict__ wv, const float* __restrict__ wo)
{
    const int z = blockIdx.z;
    const float* src;
    __nv_bfloat16 *dh, *dl;
    size_t cnt;
    if (z < 3) {
        src = (z == 0) ? q : (z == 1) ? k : v;
        dh = g_act_hi + (size_t)z * ACT_N;
        dl = g_act_lo + (size_t)z * ACT_N;
        cnt = ACT_N;
    } else {
        const int w = z - 3;
        src = (w == 0) ? wq : (w == 1) ? wk : (w == 2) ? wv : wo;
        dh = g_w_hi + (size_t)w * W_N;
        dl = g_w_lo + (size_t)w * W_N;
        cnt = W_N;
    }
    const size_t i4 = (size_t)blockIdx.x * 256 + threadIdx.x;
    if (i4 * 4 >= cnt) return;
    float4 x = ((const float4*)src)[i4];
    float xs[4] = {x.x, x.y, x.z, x.w};
    __nv_bfloat16 hs[4], ls[4];
#pragma unroll
    for (int i = 0; i < 4; i++) {
        hs[i] = __float2bfloat16(xs[i]);
        ls[i] = __float2bfloat16(xs[i] - __bfloat162float(hs[i]));
    }
    *(__nv_bfloat162*)&dh[i4 * 4]     = __nv_bfloat162(hs[0], hs[1]);
    *(__nv_bfloat162*)&dh[i4 * 4 + 2] = __nv_bfloat162(hs[2], hs[3]);
    *(__nv_bfloat162*)&dl[i4 * 4]     = __nv_bfloat162(ls[0], ls[1]);
    *(__nv_bfloat162*)&dl[i4 * 4 + 2] = __nv_bfloat162(ls[2], ls[3]);
}

// ---------------------------------------------------------------------------
// HMMA split-bf16 GEMM: C = A[M,K] @ W[N,K]^T + bias. 128x128 CTA tile,
// K=1024 in 16 chunks of 64; double-buffered cp.async; SW128 smem;
// 3 mma passes (hi*hi + hi*lo + lo*hi) into fp32 accumulators.
// Stage layout per buffer: Ah(16K) Al(16K) Bh(16K) Bl(16K) = 64KB.
// ---------------------------------------------------------------------------
#define STAGE_BYTES 65536
#define TC_SMEM (2 * STAGE_BYTES)   // 128 KB (epilogue aliases it)

__device__ __forceinline__ void gemm_tc(const __nv_bfloat16* __restrict__ Ah,
                                        const __nv_bfloat16* __restrict__ Al,
                                        const __nv_bfloat16* __restrict__ Bh,
                                        const __nv_bfloat16* __restrict__ Bl,
                                        const float* __restrict__ bias,
                                        float* __restrict__ C, bool splitHead)
{
    extern __shared__ char sm[];
    const uint32_t smb = smem_u32(sm);
    const int tid  = threadIdx.x;
    const int wid  = tid >> 5;
    const int lane = tid & 31;
    const int m0 = blockIdx.y << 7;
    const int n0 = blockIdx.x << 7;

    const int warp_m = (wid >> 2) << 6;   // 0 or 64
    const int warp_n = (wid & 3) << 5;    // 0,32,64,96

    // Global base addresses (in global space for cp.async)
    uint64_t gb[4];
    {
        const void* p0 = Ah + (size_t)m0 * 1024;
        const void* p1 = Al + (size_t)m0 * 1024;
        const void* p2 = Bh + (size_t)n0 * 1024;
        const void* p3 = Bl + (size_t)n0 * 1024;
        asm("cvta.to.global.u64 %0, %1;" : "=l"(gb[0]) : "l"(p0));
        asm("cvta.to.global.u64 %0, %1;" : "=l"(gb[1]) : "l"(p1));
        asm("cvta.to.global.u64 %0, %1;" : "=l"(gb[2]) : "l"(p2));
        asm("cvta.to.global.u64 %0, %1;" : "=l"(gb[3]) : "l"(p3));
    }

    const int lr  = tid >> 3;   // 0..31 loader row base
    const int lc  = tid & 7;    // 0..7  16B col

    // ldmatrix per-thread address components
    const int arow = warp_m + (lane & 15);
    const int a_chi = lane >> 4;                 // 0/1 (k 16B half)
    const int ax = arow & 7;
    const uint32_t arow128 = (uint32_t)arow * 128;
    const int g = lane >> 3;                     // 0..3
    const int brow = warp_n + ((g >> 1) << 3) + (lane & 7);
    const int b_chi = g & 1;
    const int bx = brow & 7;
    const uint32_t brow128 = (uint32_t)brow * 128;

    float acc[4][4][4];
#pragma unroll
    for (int mi = 0; mi < 4; mi++)
#pragma unroll
        for (int nj = 0; nj < 4; nj++)
#pragma unroll
            for (int r = 0; r < 4; r++) acc[mi][nj][r] = 0.f;

    // Loader: chunk c into stage s
    auto issue_chunk = [&](int c, int s) {
        const int k0 = c << 6;
        const uint32_t st = smb + (uint32_t)s * STAGE_BYTES;
#pragma unroll
        for (int op = 0; op < 4; op++) {
#pragma unroll
            for (int rb = 0; rb < 4; rb++) {
                const int row = (rb << 5) + lr;
                const uint64_t ga = gb[op] + ((size_t)row * 1024 + k0 + (lc << 3)) * 2;
                const uint32_t sa = st + op * 16384 + swz((uint32_t)row * 128 + (lc << 4));
                cp16(sa, ga);
            }
        }
        CP_COMMIT();
    };

    issue_chunk(0, 0);

    for (int c = 0; c < 16; c++) {
        const int bsel = c & 1;
        if (c < 15) { issue_chunk(c + 1, bsel ^ 1); CP_WAIT(1); }
        else        { CP_WAIT(0); }
        __syncthreads();

        const uint32_t st = smb + (uint32_t)bsel * STAGE_BYTES;

#pragma unroll
        for (int ks = 0; ks < 4; ks++) {
            uint32_t Ahf[4][4], Alf[4][4], Bhf[4][2], Blf[4][2];
            const uint32_t acol = (uint32_t)((((ks << 1) | a_chi) ^ ax) << 4);
            const uint32_t bcol = (uint32_t)((((ks << 1) | b_chi) ^ bx) << 4);
#pragma unroll
            for (int mi = 0; mi < 4; mi++) {
                const uint32_t ad = st + arow128 + mi * 2048 + acol;
                ldmx4(Ahf[mi], ad);
                ldmx4(Alf[mi], ad + 16384);
            }
#pragma unroll
            for (int njj = 0; njj < 2; njj++) {
                const uint32_t bd = st + 32768 + brow128 + njj * 2048 + bcol;
                uint32_t t[4];
                ldmx4(t, bd);
                Bhf[njj*2][0] = t[0]; Bhf[njj*2][1] = t[1];
                Bhf[njj*2+1][0] = t[2]; Bhf[njj*2+1][1] = t[3];
                ldmx4(t, bd + 16384);
                Blf[njj*2][0] = t[0]; Blf[njj*2][1] = t[1];
                Blf[njj*2+1][0] = t[2]; Blf[njj*2+1][1] = t[3];
            }
#pragma unroll
            for (int mi = 0; mi < 4; mi++)
#pragma unroll
                for (int nj = 0; nj < 4; nj++) {
                    mma16816(acc[mi][nj], Ahf[mi], Bhf[nj]);
                    mma16816(acc[mi][nj], Ahf[mi], Blf[nj]);
                    mma16816(acc[mi][nj], Alf[mi], Bhf[nj]);
                }
        }
        __syncthreads();
    }

    // Epilogue: acc -> smem bounce (fp32, stride 136) -> coalesced global
    float* eps = (float*)sm;
    const int eg = lane >> 2;
    const int eco = (lane & 3) << 1;
#pragma unroll
    for (int mi = 0; mi < 4; mi++)
#pragma unroll
        for (int nj = 0; nj < 4; nj++) {
            const int row0 = warp_m + (mi << 4) + eg;
            const int col  = warp_n + (nj << 3) + eco;
            *(float2*)&eps[row0 * 136 + col] = make_float2(acc[mi][nj][0], acc[mi][nj][1]);
            *(float2*)&eps[(row0 + 8) * 136 + col] = make_float2(acc[mi][nj][2], acc[mi][nj][3]);
        }
    __syncthreads();

#pragma unroll
    for (int i = 0; i < 16; i++) {
        const int idx = tid + (i << 8);     // 0..4095
        const int row = idx >> 5;
        const int c4  = idx & 31;
        const int n   = n0 + (c4 << 2);
        float4 v = *(const float4*)&eps[row * 136 + (c4 << 2)];
        const float4 bb = *(const float4*)&bias[n];
        v.x += bb.x; v.y += bb.y; v.z += bb.z; v.w += bb.w;
        const int m = m0 + row;
        if (splitHead) {
            float* base = C + (((size_t)((m >> 11) * HH + (n >> 6)) * SS) + (m & 2047)) * DK + (n & 63);
            *(float4*)base = v;
        } else {
            *(float4*)&C[(size_t)m * 1024 + n] = v;
        }
    }
}

__global__ void __launch_bounds__(256, 1)
qkv_tc_kernel(const float* __restrict__ bq, const float* __restrict__ bk,
              const float* __restrict__ bv)
{
    const int z = blockIdx.z;
    const __nv_bfloat16* Ah = g_act_hi + (size_t)z * ACT_N;
    const __nv_bfloat16* Al = g_act_lo + (size_t)z * ACT_N;
    const __nv_bfloat16* Bh = g_w_hi + (size_t)z * W_N;
    const __nv_bfloat16* Bl = g_w_lo + (size_t)z * W_N;
    const float* bias = (z == 0) ? bq : (z == 1) ? bk : bv;
    float* C = (z == 0) ? g_qh : (z == 1) ? g_kh : g_vh;
    gemm_tc(Ah, Al, Bh, Bl, bias, C, true);
}

__global__ void __launch_bounds__(256, 1)
out_tc_kernel(const float* __restrict__ bo, float* __restrict__ out)
{
    gemm_tc(g_attn_hi, g_attn_lo, g_w_hi + 3 * W_N, g_w_lo + 3 * W_N, bo, out, false);
}

// ---------------------------------------------------------------------------
// Flash attention (SIMT f32x2, known-good); epilogue writes bf16 hi/lo
// for the tensor-core output projection.
// ---------------------------------------------------------------------------
__global__ void __launch_bounds__(256, 1)
flash_kernel(const int* __restrict__ mask)
{
    extern __shared__ float smf[];
    float* Qs = smf;                  // [64][64]
    float* Ks = smf + 64 * 64;        // [64][68]  (aliased as Pt)
    float* Vs = Ks + 64 * 68;         // [64][64]

    const int b  = blockIdx.z;
    const int h  = blockIdx.y;
    const int q0 = blockIdx.x << 6;
    const int tid = threadIdx.x;
    const int ty = tid >> 4;
    const int tx = tid & 15;
    const int lr  = tid >> 4;
    const int ldq = (tid & 15) << 2;

    const float* Qg = g_qh + ((size_t)(b * HH + h) * SS + q0) * DK;
    const float* Kg = g_kh + ((size_t)(b * HH + h) * SS) * DK;
    const float* Vg = g_vh + ((size_t)(b * HH + h) * SS) * DK;

#pragma unroll
    for (int it = 0; it < 4; it++) {
        const int rr = lr + (it << 4);
        *(float4*)&Qs[rr * 64 + ldq] = *(const float4*)&Qg[(size_t)rr * 64 + ldq];
    }

    ull o2[4][2];
#pragma unroll
    for (int i = 0; i < 4; i++) { o2[i][0] = 0ull; o2[i][1] = 0ull; }
    float mrun[4] = {-3e38f, -3e38f, -3e38f, -3e38f};
    float lrun[4] = {0.f, 0.f, 0.f, 0.f};

    float4 kreg[4], vreg[4];
#pragma unroll
    for (int it = 0; it < 4; it++) {
        const int rr = lr + (it << 4);
        kreg[it] = *(const float4*)&Kg[(size_t)rr * 64 + ldq];
        vreg[it] = *(const float4*)&Vg[(size_t)rr * 64 + ldq];
    }

    for (int t = 0; t < 32; t++) {
        const int k0 = t << 6;
        __syncthreads();
#pragma unroll
        for (int it = 0; it < 4; it++) {
            const int rr = lr + (it << 4);
            *(float4*)&Ks[rr * 68 + ldq] = kreg[it];
            *(float4*)&Vs[rr * 64 + ldq] = vreg[it];
        }
        __syncthreads();

        if (t < 31) {
            const int kn = (t + 1) << 6;
#pragma unroll
            for (int it = 0; it < 4; it++) {
                const int rr = kn + lr + (it << 4);
                kreg[it] = *(const float4*)&Kg[(size_t)rr * 64 + ldq];
                vreg[it] = *(const float4*)&Vg[(size_t)rr * 64 + ldq];
            }
        }

        int mv[4][4];
#pragma unroll
        for (int i = 0; i < 4; i++) {
            const int mrow = q0 + ty + (i << 4);
#pragma unroll
            for (int j = 0; j < 4; j++)
                mv[i][j] = mask[(size_t)mrow * SS + (k0 + tx + (j << 4))];
        }

        ull s2[4][4];
#pragma unroll
        for (int i = 0; i < 4; i++)
#pragma unroll
            for (int j = 0; j < 4; j++) s2[i][j] = 0ull;

#pragma unroll
        for (int dq4 = 0; dq4 < 64; dq4 += 4) {
            ulonglong2 qv[4], kv[4];
#pragma unroll
            for (int i = 0; i < 4; i++)
                qv[i] = *(const ulonglong2*)&Qs[(ty + (i << 4)) * 64 + dq4];
#pragma unroll
            for (int j = 0; j < 4; j++)
                kv[j] = *(const ulonglong2*)&Ks[(tx + (j << 4)) * 68 + dq4];
#pragma unroll
            for (int i = 0; i < 4; i++)
#pragma unroll
                for (int j = 0; j < 4; j++) {
                    fma2(s2[i][j], qv[i].x, kv[j].x);
                    fma2(s2[i][j], qv[i].y, kv[j].y);
                }
        }

        float s[4][4];
#pragma unroll
        for (int i = 0; i < 4; i++)
#pragma unroll
            for (int j = 0; j < 4; j++) {
                float2 f = unpack2(s2[i][j]);
                s[i][j] = mv[i][j] ? (f.x + f.y) * 0.125f : -1e9f;
            }

#pragma unroll
        for (int i = 0; i < 4; i++) {
            float mx = fmaxf(fmaxf(s[i][0], s[i][1]), fmaxf(s[i][2], s[i][3]));
#pragma unroll
            for (int off = 1; off < 16; off <<= 1)
                mx = fmaxf(mx, __shfl_xor_sync(0xffffffffu, mx, off));
            const float mn = fmaxf(mrun[i], mx);
            const float alpha = __expf(mrun[i] - mn);
            mrun[i] = mn;
            float r0 = 0.f;
#pragma unroll
            for (int j = 0; j < 4; j++) {
                s[i][j] = __expf(s[i][j] - mn);
                r0 += s[i][j];
            }
#pragma unroll
            for (int off = 1; off < 16; off <<= 1)
                r0 += __shfl_xor_sync(0xffffffffu, r0, off);
            lrun[i] = lrun[i] * alpha + r0;
            ull ad = dup2(alpha);
            mul2(o2[i][0], ad);
            mul2(o2[i][1], ad);
        }

        __syncthreads();
        float* Pt = Ks;
#pragma unroll
        for (int i = 0; i < 4; i++)
#pragma unroll
            for (int j = 0; j < 4; j++)
                Pt[(ty + (i << 4)) * 68 + (tx + (j << 4))] = s[i][j];
        __syncthreads();

#pragma unroll
        for (int jq = 0; jq < 64; jq += 4) {
            float4 pv[4];
            ulonglong2 vv[4];
#pragma unroll
            for (int i = 0; i < 4; i++)
                pv[i] = *(const float4*)&Pt[(ty + (i << 4)) * 68 + jq];
#pragma unroll
            for (int u = 0; u < 4; u++)
                vv[u] = *(const ulonglong2*)&Vs[(jq + u) * 64 + (tx << 2)];
#pragma unroll
            for (int i = 0; i < 4; i++) {
                ull dx = dup2(pv[i].x), dy = dup2(pv[i].y);
                ull dz = dup2(pv[i].z), dw = dup2(pv[i].w);
                fma2(o2[i][0], dx, vv[0].x); fma2(o2[i][1], dx, vv[0].y);
                fma2(o2[i][0], dy, vv[1].x); fma2(o2[i][1], dy, vv[1].y);
                fma2(o2[i][0], dz, vv[2].x); fma2(o2[i][1], dz, vv[2].y);
                fma2(o2[i][0], dw, vv[3].x); fma2(o2[i][1], dw, vv[3].y);
            }
        }
    }

    // Epilogue: normalize; write bf16 hi/lo into [B*S, 1024] attn buffers
#pragma unroll
    for (int i = 0; i < 4; i++) {
        const float inv = 1.0f / lrun[i];
        const int r = ty + (i << 4);
        const size_t arow = ((size_t)(b * SS + q0 + r)) * DM + h * DK + (tx << 2);
        float vals[4];
        float2 f0 = unpack2(o2[i][0]);
        float2 f1 = unpack2(o2[i][1]);
        vals[0] = f0.x * inv; vals[1] = f0.y * inv;
        vals[2] = f1.x * inv; vals[3] = f1.y * inv;
        __nv_bfloat16 hs[4], ls[4];
#pragma unroll
        for (int jj = 0; jj < 4; jj++) {
            hs[jj] = __float2bfloat16(vals[jj]);
            ls[jj] = __float2bfloat16(vals[jj] - __bfloat162float(hs[jj]));
        }
        *(__nv_bfloat162*)&g_attn_hi[arow]     = __nv_bfloat162(hs[0], hs[1]);
        *(__nv_bfloat162*)&g_attn_hi[arow + 2] = __nv_bfloat162(hs[2], hs[3]);
        *(__nv_bfloat162*)&g_attn_lo[arow]     = __nv_bfloat162(ls[0], ls[1]);
        *(__nv_bfloat162*)&g_attn_lo[arow + 2] = __nv_bfloat162(ls[2], ls[3]);
    }
}

// ---------------------------------------------------------------------------
extern "C" void kernel_launch(void* const* d_in, const int* in_sizes, int n_in,
                              void* d_out, int out_size)
{
    const float* q    = (const float*)d_in[0];
    const float* k    = (const float*)d_in[1];
    const float* v    = (const float*)d_in[2];
    const int*   mask = (const int*)  d_in[3];
    const float* wq   = (const float*)d_in[4];
    const float* bq   = (const float*)d_in[5];
    const float* wk   = (const float*)d_in[6];
    const float* bk   = (const float*)d_in[7];
    const float* wv   = (const float*)d_in[8];
    const float* bv   = (const float*)d_in[9];
    const float* wo   = (const float*)d_in[10];
    const float* bo   = (const float*)d_in[11];
    float* out = (float*)d_out;

    const int FLASH_SMEM = (64 * 64 + 64 * 68 + 64 * 64) * 4;  // 50176 B
    cudaFuncSetAttribute(flash_kernel, cudaFuncAttributeMaxDynamicSharedMemorySize,
                         FLASH_SMEM);
    cudaFuncSetAttribute(qkv_tc_kernel, cudaFuncAttributeMaxDynamicSharedMemorySize,
                         TC_SMEM);
    cudaFuncSetAttribute(out_tc_kernel, cudaFuncAttributeMaxDynamicSharedMemorySize,
                         TC_SMEM);

    dim3 blk(256);
    split_kernel<<<dim3(4096, 1, 7), blk>>>(q, k, v, wq, wk, wv, wo);
    qkv_tc_kernel<<<dim3(8, 32, 3), blk, TC_SMEM>>>(bq, bk, bv);
    flash_kernel<<<dim3(32, 16, 2), blk, FLASH_SMEM>>>(mask);
    out_tc_kernel<<<dim3(8, 32, 1), blk, TC_SMEM>>>(bo, out);
}

// round 7
// speedup vs baseline: 2.9904x; 1.9099x over previous
#include <cuda_runtime.h>
#include <cuda_bf16.h>
#include <cstdint>

#define BB 2
#define SS 2048
#define DM 1024
#define HH 16
#define DK 64

typedef unsigned long long ull;

#define ACT_N ((size_t)4096 * 1024)
#define W_N   ((size_t)1024 * 1024)

// Scratch (__device__ globals; allocation-free rule)
__device__ __align__(16) __nv_bfloat16 g_act_hi[3 * ACT_N];   // q,k,v inputs split
__device__ __align__(16) __nv_bfloat16 g_act_lo[3 * ACT_N];
__device__ __align__(16) __nv_bfloat16 g_w_hi[4 * W_N];       // wq,wk,wv,wo split
__device__ __align__(16) __nv_bfloat16 g_w_lo[4 * W_N];
__device__ __align__(16) __nv_bfloat16 g_q_hi[BB*HH*SS*DK];   // [BH][S][64] (x0.125)
__device__ __align__(16) __nv_bfloat16 g_q_lo[BB*HH*SS*DK];
__device__ __align__(16) __nv_bfloat16 g_k_hi[BB*HH*SS*DK];   // [BH][S][64]
__device__ __align__(16) __nv_bfloat16 g_k_lo[BB*HH*SS*DK];
__device__ __align__(16) __nv_bfloat16 g_vt_hi[BB*HH*SS*DK];  // [BH][64][S]  (V^T)
__device__ __align__(16) __nv_bfloat16 g_vt_lo[BB*HH*SS*DK];
__device__ __align__(16) __nv_bfloat16 g_attn_hi[ACT_N];      // flash out split
__device__ __align__(16) __nv_bfloat16 g_attn_lo[ACT_N];

// ---------------- helpers ----------------
__device__ __forceinline__ uint32_t smem_u32(const void* p) {
    uint32_t a;
    asm("{ .reg .u64 t; cvta.to.shared.u64 t, %1; cvt.u32.u64 %0, t; }"
        : "=r"(a) : "l"(p));
    return a;
}
__device__ __forceinline__ uint64_t gmem_u64(const void* p) {
    uint64_t a;
    asm("cvta.to.global.u64 %0, %1;" : "=l"(a) : "l"(p));
    return a;
}
// mma.sync m16n8k16 bf16 -> fp32
__device__ __forceinline__ void mma16816(float* c, const uint32_t* a, const uint32_t* b) {
    asm volatile(
        "mma.sync.aligned.m16n8k16.row.col.f32.bf16.bf16.f32 "
        "{%0,%1,%2,%3}, {%4,%5,%6,%7}, {%8,%9}, {%0,%1,%2,%3};"
        : "+f"(c[0]), "+f"(c[1]), "+f"(c[2]), "+f"(c[3])
        : "r"(a[0]), "r"(a[1]), "r"(a[2]), "r"(a[3]), "r"(b[0]), "r"(b[1]));
}
__device__ __forceinline__ void ldmx4(uint32_t* r, uint32_t addr) {
    asm volatile("ldmatrix.sync.aligned.m8n8.x4.shared.b16 {%0,%1,%2,%3}, [%4];"
                 : "=r"(r[0]), "=r"(r[1]), "=r"(r[2]), "=r"(r[3]) : "r"(addr));
}
__device__ __forceinline__ void cp16(uint32_t saddr, uint64_t gaddr) {
    asm volatile("cp.async.cg.shared.global [%0], [%1], 16;"
                 :: "r"(saddr), "l"(gaddr) : "memory");
}
#define CP_COMMIT() asm volatile("cp.async.commit_group;" ::: "memory")
#define CP_WAIT(n)  asm volatile("cp.async.wait_group %0;" :: "n"(n) : "memory")

__device__ __forceinline__ uint32_t swz(uint32_t x) { return x ^ ((x >> 3) & 0x70); }

// pack two fp32 -> bf16x2 hi + bf16x2 residual lo   (lo half = x0, hi half = x1)
__device__ __forceinline__ void pack_hilo(float x0, float x1, uint32_t& hi, uint32_t& lo) {
    uint32_t h;
    asm("cvt.rn.bf16x2.f32 %0, %1, %2;" : "=r"(h) : "f"(x1), "f"(x0));
    const float h0 = __uint_as_float(h << 16);
    const float h1 = __uint_as_float(h & 0xffff0000u);
    uint32_t l;
    asm("cvt.rn.bf16x2.f32 %0, %1, %2;" : "=r"(l) : "f"(x1 - h1), "f"(x0 - h0));
    hi = h; lo = l;
}

// ---------------------------------------------------------------------------
// Split fp32 -> bf16 hi/lo.  z=0..2: q,k,v inputs ; z=3..6: wq,wk,wv,wo
// ---------------------------------------------------------------------------
__global__ void __launch_bounds__(256)
split_kernel(const float* __restrict__ q, const float* __restrict__ k,
             const float* __restrict__ v,
             const float* __restrict__ wq, const float* __restrict__ wk,
             const float* __restrict__ wv, const float* __restrict__ wo)
{
    const int z = blockIdx.z;
    const float* src;
    __nv_bfloat16 *dh, *dl;
    size_t cnt;
    if (z < 3) {
        src = (z == 0) ? q : (z == 1) ? k : v;
        dh = g_act_hi + (size_t)z * ACT_N;
        dl = g_act_lo + (size_t)z * ACT_N;
        cnt = ACT_N;
    } else {
        const int w = z - 3;
        src = (w == 0) ? wq : (w == 1) ? wk : (w == 2) ? wv : wo;
        dh = g_w_hi + (size_t)w * W_N;
        dl = g_w_lo + (size_t)w * W_N;
        cnt = W_N;
    }
    const size_t i4 = (size_t)blockIdx.x * 256 + threadIdx.x;
    if (i4 * 4 >= cnt) return;
    float4 x = ((const float4*)src)[i4];
    uint32_t h01, l01, h23, l23;
    pack_hilo(x.x, x.y, h01, l01);
    pack_hilo(x.z, x.w, h23, l23);
    *(uint2*)&dh[i4 * 4] = make_uint2(h01, h23);
    *(uint2*)&dl[i4 * 4] = make_uint2(l01, l23);
}

// ---------------------------------------------------------------------------
// HMMA split-bf16 GEMM: C = A[M,K] @ W[N,K]^T (+bias). 128x128 CTA tile,
// K=1024, 16 chunks, double-buffered cp.async, SW128 smem, 3 mma passes.
// MODE 0: fp32 out (out_proj). MODE 1: q/k -> bf16 hi/lo split-head, xscale.
// MODE 2: V^T -> bf16 hi/lo [BH][64][S] (A = Wv rows, B = X rows; bias by m).
// ---------------------------------------------------------------------------
#define STAGE_BYTES 65536
#define TC_SMEM (2 * STAGE_BYTES)

template <int MODE>
__device__ __forceinline__ void gemm_tc(const __nv_bfloat16* __restrict__ Ah,
                                        const __nv_bfloat16* __restrict__ Al,
                                        const __nv_bfloat16* __restrict__ Bh,
                                        const __nv_bfloat16* __restrict__ Bl,
                                        const float* __restrict__ bias,
                                        float* __restrict__ C,
                                        __nv_bfloat16* __restrict__ Dh,
                                        __nv_bfloat16* __restrict__ Dl,
                                        float oscale)
{
    extern __shared__ char sm[];
    const uint32_t smb = smem_u32(sm);
    const int tid  = threadIdx.x;
    const int wid  = tid >> 5;
    const int lane = tid & 31;
    const int m0 = blockIdx.y << 7;
    const int n0 = blockIdx.x << 7;

    const int warp_m = (wid >> 2) << 6;
    const int warp_n = (wid & 3) << 5;

    uint64_t gb[4];
    gb[0] = gmem_u64(Ah + (size_t)m0 * 1024);
    gb[1] = gmem_u64(Al + (size_t)m0 * 1024);
    gb[2] = gmem_u64(Bh + (size_t)n0 * 1024);
    gb[3] = gmem_u64(Bl + (size_t)n0 * 1024);

    const int lr = tid >> 3;
    const int lc = tid & 7;

    const int arow = warp_m + (lane & 15);
    const int a_chi = lane >> 4;
    const int ax = arow & 7;
    const uint32_t arow128 = (uint32_t)arow * 128;
    const int g = lane >> 3;
    const int brow = warp_n + ((g >> 1) << 3) + (lane & 7);
    const int b_chi = g & 1;
    const int bx = brow & 7;
    const uint32_t brow128 = (uint32_t)brow * 128;

    float acc[4][4][4];
#pragma unroll
    for (int mi = 0; mi < 4; mi++)
#pragma unroll
        for (int nj = 0; nj < 4; nj++)
#pragma unroll
            for (int r = 0; r < 4; r++) acc[mi][nj][r] = 0.f;

    auto issue_chunk = [&](int c, int s) {
        const int k0 = c << 6;
        const uint32_t st = smb + (uint32_t)s * STAGE_BYTES;
#pragma unroll
        for (int op = 0; op < 4; op++) {
#pragma unroll
            for (int rb = 0; rb < 4; rb++) {
                const int row = (rb << 5) + lr;
                const uint64_t ga = gb[op] + ((size_t)row * 1024 + k0 + (lc << 3)) * 2;
                const uint32_t sa = st + op * 16384 + swz((uint32_t)row * 128 + (lc << 4));
                cp16(sa, ga);
            }
        }
        CP_COMMIT();
    };

    issue_chunk(0, 0);

    for (int c = 0; c < 16; c++) {
        const int bsel = c & 1;
        if (c < 15) { issue_chunk(c + 1, bsel ^ 1); CP_WAIT(1); }
        else        { CP_WAIT(0); }
        __syncthreads();

        const uint32_t st = smb + (uint32_t)bsel * STAGE_BYTES;

#pragma unroll
        for (int ks = 0; ks < 4; ks++) {
            uint32_t Ahf[4][4], Alf[4][4], Bhf[4][2], Blf[4][2];
            const uint32_t acol = (uint32_t)((((ks << 1) | a_chi) ^ ax) << 4);
            const uint32_t bcol = (uint32_t)((((ks << 1) | b_chi) ^ bx) << 4);
#pragma unroll
            for (int mi = 0; mi < 4; mi++) {
                const uint32_t ad = st + arow128 + mi * 2048 + acol;
                ldmx4(Ahf[mi], ad);
                ldmx4(Alf[mi], ad + 16384);
            }
#pragma unroll
            for (int njj = 0; njj < 2; njj++) {
                const uint32_t bd = st + 32768 + brow128 + njj * 2048 + bcol;
                uint32_t t[4];
                ldmx4(t, bd);
                Bhf[njj*2][0] = t[0]; Bhf[njj*2][1] = t[1];
                Bhf[njj*2+1][0] = t[2]; Bhf[njj*2+1][1] = t[3];
                ldmx4(t, bd + 16384);
                Blf[njj*2][0] = t[0]; Blf[njj*2][1] = t[1];
                Blf[njj*2+1][0] = t[2]; Blf[njj*2+1][1] = t[3];
            }
#pragma unroll
            for (int mi = 0; mi < 4; mi++)
#pragma unroll
                for (int nj = 0; nj < 4; nj++) {
                    mma16816(acc[mi][nj], Ahf[mi], Bhf[nj]);
                    mma16816(acc[mi][nj], Ahf[mi], Blf[nj]);
                    mma16816(acc[mi][nj], Alf[mi], Bhf[nj]);
                }
        }
        __syncthreads();
    }

    // Epilogue via fp32 smem bounce
    float* eps = (float*)sm;
    const int eg = lane >> 2;
    const int eco = (lane & 3) << 1;
#pragma unroll
    for (int mi = 0; mi < 4; mi++)
#pragma unroll
        for (int nj = 0; nj < 4; nj++) {
            const int row0 = warp_m + (mi << 4) + eg;
            const int col  = warp_n + (nj << 3) + eco;
            *(float2*)&eps[row0 * 136 + col] = make_float2(acc[mi][nj][0], acc[mi][nj][1]);
            *(float2*)&eps[(row0 + 8) * 136 + col] = make_float2(acc[mi][nj][2], acc[mi][nj][3]);
        }
    __syncthreads();

#pragma unroll
    for (int i = 0; i < 16; i++) {
        const int idx = tid + (i << 8);
        const int row = idx >> 5;
        const int c4  = idx & 31;
        const int n   = n0 + (c4 << 2);
        const int m   = m0 + row;
        float4 v = *(const float4*)&eps[row * 136 + (c4 << 2)];
        if (MODE == 2) {
            const float bb = bias[m];
            v.x += bb; v.y += bb; v.z += bb; v.w += bb;
        } else {
            const float4 bb = *(const float4*)&bias[n];
            v.x += bb.x; v.y += bb.y; v.z += bb.z; v.w += bb.w;
        }
        if (MODE == 0) {
            *(float4*)&C[(size_t)m * 1024 + n] = v;
        } else if (MODE == 1) {
            v.x *= oscale; v.y *= oscale; v.z *= oscale; v.w *= oscale;
            const int bq_ = m >> 11, s = m & 2047, h0 = n >> 6, d = n & 63;
            const size_t base = (((size_t)(bq_ * HH + h0)) * SS + s) * DK + d;
            uint32_t h01, l01, h23, l23;
            pack_hilo(v.x, v.y, h01, l01);
            pack_hilo(v.z, v.w, h23, l23);
            *(uint2*)&Dh[base] = make_uint2(h01, h23);
            *(uint2*)&Dl[base] = make_uint2(l01, l23);
        } else {
            // MODE 2: m = d_total (Wv row), n = token
            const int h0 = m >> 6, d = m & 63, bq_ = n >> 11, s = n & 2047;
            const size_t base = (((size_t)(bq_ * HH + h0)) * DK + d) * SS + s;
            uint32_t h01, l01, h23, l23;
            pack_hilo(v.x, v.y, h01, l01);
            pack_hilo(v.z, v.w, h23, l23);
            *(uint2*)&Dh[base] = make_uint2(h01, h23);
            *(uint2*)&Dl[base] = make_uint2(l01, l23);
        }
    }
}

__global__ void __launch_bounds__(256, 1)
qkv_tc_kernel(const float* __restrict__ bq, const float* __restrict__ bk)
{
    const int z = blockIdx.z;   // 0=q, 1=k
    const __nv_bfloat16* Ah = g_act_hi + (size_t)z * ACT_N;
    const __nv_bfloat16* Al = g_act_lo + (size_t)z * ACT_N;
    const __nv_bfloat16* Bh = g_w_hi + (size_t)z * W_N;
    const __nv_bfloat16* Bl = g_w_lo + (size_t)z * W_N;
    if (z == 0)
        gemm_tc<1>(Ah, Al, Bh, Bl, bq, nullptr, g_q_hi, g_q_lo, 0.125f);
    else
        gemm_tc<1>(Ah, Al, Bh, Bl, bk, nullptr, g_k_hi, g_k_lo, 1.0f);
}

__global__ void __launch_bounds__(256, 1)
v_tc_kernel(const float* __restrict__ bv)
{
    // Roles swapped: A = Wv rows (M=1024), B = X rows (N=4096) -> C = V^T
    gemm_tc<2>(g_w_hi + 2 * W_N, g_w_lo + 2 * W_N,
               g_act_hi + 2 * ACT_N, g_act_lo + 2 * ACT_N,
               bv, nullptr, g_vt_hi, g_vt_lo, 1.0f);
}

__global__ void __launch_bounds__(256, 1)
out_tc_kernel(const float* __restrict__ bo, float* __restrict__ out)
{
    gemm_tc<0>(g_attn_hi, g_attn_lo, g_w_hi + 3 * W_N, g_w_lo + 3 * W_N,
               bo, out, nullptr, nullptr, 1.0f);
}

// ---------------------------------------------------------------------------
// Flash attention on mma.sync. CTA = 128 q-rows x full S; 8 warps, each m16.
// Q frags in registers; K/V^T hi/lo double-buffered cp.async; P stays in regs
// (QK C-fragment == PV A-fragment after bf16x2 hi/lo packing).
// smem: [0,32K) stage0 (Khi,Klo,Vhi,Vlo 8K each), [32K,64K) stage1.
// Q staged once in [0,32K) before the pipeline starts.
// ---------------------------------------------------------------------------
#define FLASH_SMEM 65536

__global__ void __launch_bounds__(256, 1)
flash_mma_kernel(const int* __restrict__ mask)
{
    extern __shared__ char sm[];
    const uint32_t smb = smem_u32(sm);
    const int tid  = threadIdx.x;
    const int wid  = tid >> 5;
    const int lane = tid & 31;
    const int b = blockIdx.z, h = blockIdx.y;
    const int bh = b * HH + h;
    const int q0 = blockIdx.x << 7;

    const int lr = tid >> 3;
    const int lc = tid & 7;

    // ---- stage Q (hi/lo) and ldmatrix to registers
    {
        const uint64_t gq0 = gmem_u64(g_q_hi + ((size_t)bh * SS + q0) * DK);
        const uint64_t gq1 = gmem_u64(g_q_lo + ((size_t)bh * SS + q0) * DK);
#pragma unroll
        for (int rs = 0; rs < 4; rs++) {
            const int row = (rs << 5) + lr;
            const uint64_t off = ((size_t)row * 64 + (lc << 3)) * 2;
            const uint32_t sa = swz((uint32_t)row * 128 + (lc << 4));
            cp16(smb + sa, gq0 + off);
            cp16(smb + 16384 + sa, gq1 + off);
        }
        CP_COMMIT(); CP_WAIT(0);
        __syncthreads();
    }
    uint32_t qh[4][4], ql[4][4];
    {
        const int arow = (wid << 4) + (lane & 15);
        const int a_chi = lane >> 4;
        const int ax = arow & 7;
#pragma unroll
        for (int ks = 0; ks < 4; ks++) {
            const uint32_t col = (uint32_t)((((ks << 1) | a_chi) ^ ax) << 4);
            ldmx4(qh[ks], smb + (uint32_t)arow * 128 + col);
            ldmx4(ql[ks], smb + 16384 + (uint32_t)arow * 128 + col);
        }
    }
    __syncthreads();

    const uint64_t gkh = gmem_u64(g_k_hi + (size_t)bh * SS * DK);
    const uint64_t gkl = gmem_u64(g_k_lo + (size_t)bh * SS * DK);
    const uint64_t gvh = gmem_u64(g_vt_hi + (size_t)bh * DK * SS);
    const uint64_t gvl = gmem_u64(g_vt_lo + (size_t)bh * DK * SS);

    auto issue = [&](int t, int s) {
        const uint32_t st = smb + (uint32_t)s * 32768;
        const int kv0 = t << 6;
#pragma unroll
        for (int arr = 0; arr < 4; arr++) {
#pragma unroll
            for (int rs = 0; rs < 2; rs++) {
                const int row = (rs << 5) + lr;
                uint64_t ga;
                if (arr < 2)
                    ga = (arr == 0 ? gkh : gkl) + (((size_t)(kv0 + row)) * 64 + (lc << 3)) * 2;
                else
                    ga = (arr == 2 ? gvh : gvl) + ((size_t)row * SS + kv0 + (lc << 3)) * 2;
                cp16(st + arr * 8192 + swz((uint32_t)row * 128 + (lc << 4)), ga);
            }
        }
        CP_COMMIT();
    };

    issue(0, 0);

    const int gq = lane >> 3;
    const int brl = ((gq >> 1) << 3) | (lane & 7);
    const int bchi = gq & 1;
    const int bxr = brl & 7;

    const int r0 = q0 + (wid << 4) + (lane >> 2);
    const int* mrow0 = mask + (size_t)r0 * SS;
    const int* mrow1 = mask + (size_t)(r0 + 8) * SS;
    const int cbase = (lane & 3) << 1;

    float o[8][4];
#pragma unroll
    for (int nj = 0; nj < 8; nj++)
#pragma unroll
        for (int r = 0; r < 4; r++) o[nj][r] = 0.f;
    float m0 = -3e38f, m1 = -3e38f, l0 = 0.f, l1 = 0.f;

    for (int t = 0; t < 32; t++) {
        const int bsel = t & 1;
        if (t < 31) { issue(t + 1, bsel ^ 1); CP_WAIT(1); }
        else        { CP_WAIT(0); }
        __syncthreads();
        const uint32_t st = smb + (uint32_t)bsel * 32768;
        const int kv0 = t << 6;

        // ---- S = Q K^T (3-pass split)
        float sc[8][4];
#pragma unroll
        for (int nj = 0; nj < 8; nj++)
#pragma unroll
            for (int r = 0; r < 4; r++) sc[nj][r] = 0.f;

#pragma unroll
        for (int ks = 0; ks < 4; ks++) {
            const uint32_t col = (uint32_t)((((ks << 1) | bchi) ^ bxr) << 4);
#pragma unroll
            for (int njj = 0; njj < 4; njj++) {
                const uint32_t rb = st + (uint32_t)((njj << 4) + brl) * 128 + col;
                uint32_t tH[4], tL[4];
                ldmx4(tH, rb);
                ldmx4(tL, rb + 8192);
                mma16816(sc[2*njj],   qh[ks], tH);
                mma16816(sc[2*njj],   qh[ks], tL);
                mma16816(sc[2*njj],   ql[ks], tH);
                mma16816(sc[2*njj+1], qh[ks], tH + 2);
                mma16816(sc[2*njj+1], qh[ks], tL + 2);
                mma16816(sc[2*njj+1], ql[ks], tH + 2);
            }
        }

        // ---- mask + online softmax (scale already folded into Q)
        float mx0 = -3e38f, mx1 = -3e38f;
#pragma unroll
        for (int nj = 0; nj < 8; nj++) {
            const int kc = kv0 + (nj << 3) + cbase;
            const int2 mv0 = *(const int2*)&mrow0[kc];
            const int2 mv1 = *(const int2*)&mrow1[kc];
            sc[nj][0] = mv0.x ? sc[nj][0] : -1e9f;
            sc[nj][1] = mv0.y ? sc[nj][1] : -1e9f;
            sc[nj][2] = mv1.x ? sc[nj][2] : -1e9f;
            sc[nj][3] = mv1.y ? sc[nj][3] : -1e9f;
            mx0 = fmaxf(mx0, fmaxf(sc[nj][0], sc[nj][1]));
            mx1 = fmaxf(mx1, fmaxf(sc[nj][2], sc[nj][3]));
        }
        mx0 = fmaxf(mx0, __shfl_xor_sync(0xffffffffu, mx0, 1));
        mx0 = fmaxf(mx0, __shfl_xor_sync(0xffffffffu, mx0, 2));
        mx1 = fmaxf(mx1, __shfl_xor_sync(0xffffffffu, mx1, 1));
        mx1 = fmaxf(mx1, __shfl_xor_sync(0xffffffffu, mx1, 2));

        const float mn0 = fmaxf(m0, mx0);
        const float mn1 = fmaxf(m1, mx1);
        const float a0 = __expf(m0 - mn0);
        const float a1 = __expf(m1 - mn1);
        m0 = mn0; m1 = mn1;

        float s0 = 0.f, s1 = 0.f;
#pragma unroll
        for (int nj = 0; nj < 8; nj++) {
            sc[nj][0] = __expf(sc[nj][0] - mn0);
            sc[nj][1] = __expf(sc[nj][1] - mn0);
            sc[nj][2] = __expf(sc[nj][2] - mn1);
            sc[nj][3] = __expf(sc[nj][3] - mn1);
            s0 += sc[nj][0] + sc[nj][1];
            s1 += sc[nj][2] + sc[nj][3];
        }
        s0 += __shfl_xor_sync(0xffffffffu, s0, 1);
        s0 += __shfl_xor_sync(0xffffffffu, s0, 2);
        s1 += __shfl_xor_sync(0xffffffffu, s1, 1);
        s1 += __shfl_xor_sync(0xffffffffu, s1, 2);
        l0 = l0 * a0 + s0;
        l1 = l1 * a1 + s1;

#pragma unroll
        for (int nj = 0; nj < 8; nj++) {
            o[nj][0] *= a0; o[nj][1] *= a0;
            o[nj][2] *= a1; o[nj][3] *= a1;
        }

        // ---- O += P V (P in regs; 3-pass split)
#pragma unroll
        for (int kt = 0; kt < 4; kt++) {
            uint32_t ah[4], al[4];
            pack_hilo(sc[2*kt][0],   sc[2*kt][1],   ah[0], al[0]);
            pack_hilo(sc[2*kt][2],   sc[2*kt][3],   ah[1], al[1]);
            pack_hilo(sc[2*kt+1][0], sc[2*kt+1][1], ah[2], al[2]);
            pack_hilo(sc[2*kt+1][2], sc[2*kt+1][3], ah[3], al[3]);
            const uint32_t col = (uint32_t)((((kt << 1) | bchi) ^ bxr) << 4);
#pragma unroll
            for (int njj = 0; njj < 4; njj++) {
                const uint32_t rb = st + 16384 + (uint32_t)((njj << 4) + brl) * 128 + col;
                uint32_t vH[4], vL[4];
                ldmx4(vH, rb);
                ldmx4(vL, rb + 8192);
                mma16816(o[2*njj],   ah, vH);
                mma16816(o[2*njj],   ah, vL);
                mma16816(o[2*njj],   al, vH);
                mma16816(o[2*njj+1], ah, vH + 2);
                mma16816(o[2*njj+1], ah, vL + 2);
                mma16816(o[2*njj+1], al, vH + 2);
            }
        }
        __syncthreads();
    }

    // ---- epilogue: normalize, split hi/lo, write [B*S, 1024]
    const float i0 = 1.0f / l0;
    const float i1 = 1.0f / l1;
    const size_t ro0 = ((size_t)(b * SS + q0 + (wid << 4) + (lane >> 2))) * DM + h * DK;
    const size_t ro1 = ro0 + (size_t)8 * DM;
#pragma unroll
    for (int nj = 0; nj < 8; nj++) {
        const int colg = (nj << 3) + cbase;
        uint32_t hi, lo;
        pack_hilo(o[nj][0] * i0, o[nj][1] * i0, hi, lo);
        *(uint32_t*)&g_attn_hi[ro0 + colg] = hi;
        *(uint32_t*)&g_attn_lo[ro0 + colg] = lo;
        pack_hilo(o[nj][2] * i1, o[nj][3] * i1, hi, lo);
        *(uint32_t*)&g_attn_hi[ro1 + colg] = hi;
        *(uint32_t*)&g_attn_lo[ro1 + colg] = lo;
    }
}

// ---------------------------------------------------------------------------
extern "C" void kernel_launch(void* const* d_in, const int* in_sizes, int n_in,
                              void* d_out, int out_size)
{
    const float* q    = (const float*)d_in[0];
    const float* k    = (const float*)d_in[1];
    const float* v    = (const float*)d_in[2];
    const int*   mask = (const int*)  d_in[3];
    const float* bq   = (const float*)d_in[5];
    const float* bk   = (const float*)d_in[7];
    const float* bv   = (const float*)d_in[9];
    const float* bo   = (const float*)d_in[11];
    const float* wq   = (const float*)d_in[4];
    const float* wk   = (const float*)d_in[6];
    const float* wv   = (const float*)d_in[8];
    const float* wo   = (const float*)d_in[10];
    float* out = (float*)d_out;

    cudaFuncSetAttribute(qkv_tc_kernel, cudaFuncAttributeMaxDynamicSharedMemorySize, TC_SMEM);
    cudaFuncSetAttribute(v_tc_kernel, cudaFuncAttributeMaxDynamicSharedMemorySize, TC_SMEM);
    cudaFuncSetAttribute(out_tc_kernel, cudaFuncAttributeMaxDynamicSharedMemorySize, TC_SMEM);
    cudaFuncSetAttribute(flash_mma_kernel, cudaFuncAttributeMaxDynamicSharedMemorySize, FLASH_SMEM);

    dim3 blk(256);
    split_kernel<<<dim3(4096, 1, 7), blk>>>(q, k, v, wq, wk, wv, wo);
    qkv_tc_kernel<<<dim3(8, 32, 2), blk, TC_SMEM>>>(bq, bk);
    v_tc_kernel<<<dim3(32, 8, 1), blk, TC_SMEM>>>(bv);
    flash_mma_kernel<<<dim3(16, 16, 2), blk, FLASH_SMEM>>>(mask);
    out_tc_kernel<<<dim3(8, 32, 1), blk, TC_SMEM>>>(bo, out);
}